// round 15
// baseline (speedup 1.0000x reference)
#include <cuda_runtime.h>
#include <cuda.h>
#include <cuda_bf16.h>
#include <math.h>
#include <stdint.h>

#define BB 2
#define TT 2048
#define DD 1024
#define HH 16
#define DH 64
#define LL 6
#define VV 50257
#define FF 4096
#define MM_ (BB*TT)
#define KMIN (TT-512)
#define VPAD 50432
#define QKVN 3072

#if !defined(__CUDA_ARCH__) || defined(__CUDA_ARCH_FEAT_SM103_ALL) || defined(__CUDA_ARCH_FEAT_SM100_ALL)
#define HAS_TC 1
#else
#define HAS_TC 0
#endif

__device__ float         g_x  [MM_*DD];
__device__ __nv_bfloat16 g_hh [MM_*DD];
__device__ __nv_bfloat16 g_hl [MM_*DD];
__device__ __nv_bfloat16 g_yh [MM_*DD];
__device__ __nv_bfloat16 g_yl [MM_*DD];
__device__ __nv_bfloat16 g_m1h[(size_t)MM_*FF];
__device__ __nv_bfloat16 g_m1l[(size_t)MM_*FF];
__device__ __nv_bfloat16 g_qah[BB*HH*TT*DH];
__device__ __nv_bfloat16 g_qal[BB*HH*TT*DH];
__device__ __nv_bfloat16 g_kah[BB*HH*TT*DH];
__device__ __nv_bfloat16 g_kal[BB*HH*TT*DH];
__device__ __nv_bfloat16 g_vth[BB*HH*TT*DH];
__device__ __nv_bfloat16 g_vtl[BB*HH*TT*DH];
__device__ __nv_bfloat16 g_wqkvh[(size_t)LL*QKVN*DD];
__device__ __nv_bfloat16 g_wqkvl[(size_t)LL*QKVN*DD];
__device__ __nv_bfloat16 g_wph[(size_t)LL*DD*DD];
__device__ __nv_bfloat16 g_wpl[(size_t)LL*DD*DD];
__device__ __nv_bfloat16 g_w1h[(size_t)LL*FF*DD];
__device__ __nv_bfloat16 g_w1l[(size_t)LL*FF*DD];
__device__ __nv_bfloat16 g_w2h[(size_t)LL*DD*FF];
__device__ __nv_bfloat16 g_w2l[(size_t)LL*DD*FF];
__device__ __nv_bfloat16 g_whh[(size_t)VPAD*DD];
__device__ __nv_bfloat16 g_whl[(size_t)VPAD*DD];
__device__ float         g_bqkv[LL*QKVN];

static __device__ __forceinline__ uint32_t smem_u32(const void* p){
    uint32_t a;
    asm("{ .reg .u64 t; cvta.to.shared.u64 t, %1; cvt.u32.u64 %0, t; }":"=r"(a):"l"(p));
    return a;
}
static __device__ __forceinline__ void split_bf16(float v, __nv_bfloat16& hi, __nv_bfloat16& lo){
    hi = __float2bfloat16(v);
    lo = __float2bfloat16(v - __bfloat162float(hi));
}
#if HAS_TC
static __device__ __forceinline__ uint32_t elect_one(){
    uint32_t r;
    asm volatile("{ .reg .pred p; elect.sync _|p, 0xFFFFFFFF; selp.b32 %0,1,0,p; }":"=r"(r));
    return r;
}
static __device__ __forceinline__ uint32_t ctarank(){
    uint32_t r; asm("mov.u32 %0, %%cluster_ctarank;" : "=r"(r)); return r;
}
static __device__ __forceinline__ void cluster_sync(){
    asm volatile("barrier.cluster.arrive.aligned;" ::: "memory");
    asm volatile("barrier.cluster.wait.aligned;" ::: "memory");
}
static __device__ __forceinline__ void mbar_init(uint32_t a, uint32_t c){
    asm volatile("mbarrier.init.shared.b64 [%0], %1;" :: "r"(a), "r"(c) : "memory");
}
static __device__ __forceinline__ void mbar_wait(uint32_t a, uint32_t ph){
    asm volatile("{\n\t.reg .pred P;\nWL_%=:\n\t"
        "mbarrier.try_wait.parity.acquire.cta.shared::cta.b64 P, [%0], %1;\n\t"
        "@!P bra WL_%=;\n\t}" :: "r"(a), "r"(ph) : "memory");
}
static __device__ __forceinline__ void mbar_expect(uint32_t a, uint32_t bytes){
    asm volatile("mbarrier.arrive.expect_tx.shared.b64 _, [%0], %1;"
                 :: "r"(a), "r"(bytes) : "memory");
}
static __device__ __forceinline__ void mbar_arrive_rank0(uint32_t a){
    asm volatile("{\n\t.reg .b32 ra;\n\tmapa.shared::cluster.u32 ra, %0, 0;\n\t"
        "mbarrier.arrive.shared::cluster.b64 _, [ra];\n\t}" :: "r"(a) : "memory");
}
static __device__ __forceinline__ void tma3d(uint32_t smem, const void* map,
                                             int x, int y, int z, uint32_t mbar){
    asm volatile("cp.async.bulk.tensor.3d.shared::cta.global.tile.mbarrier::complete_tx::bytes "
        "[%0], [%1, {%2, %3, %4}], [%5];"
        :: "r"(smem), "l"(map), "r"(x), "r"(y), "r"(z), "r"(mbar) : "memory");
}
static __device__ __forceinline__ uint64_t mk_desc(uint32_t addr){
    return (uint64_t(2)<<61)|(uint64_t(1)<<46)|(uint64_t(64)<<32)|(uint64_t(1)<<16)
         |((uint64_t)(addr>>4)&0x3FFF);
}
static __device__ __forceinline__ void mma_f16_ss(uint32_t d, uint64_t ad, uint64_t bd,
                                                  uint32_t idesc, uint32_t en){
    asm volatile("{\n\t.reg .pred p;\n\tsetp.ne.u32 p, %4, 0;\n\t"
        "tcgen05.mma.cta_group::1.kind::f16 [%0], %1, %2, %3, {%5,%5,%5,%5}, p;\n\t}"
        :: "r"(d), "l"(ad), "l"(bd), "r"(idesc), "r"(en), "r"(0u) : "memory");
}
static __device__ __forceinline__ void mma_f16_ss2(uint32_t d, uint64_t ad, uint64_t bd,
                                                   uint32_t idesc, uint32_t en){
    asm volatile("{\n\t.reg .pred p;\n\tsetp.ne.u32 p, %4, 0;\n\t"
        "tcgen05.mma.cta_group::2.kind::f16 [%0], %1, %2, %3, {%5,%5,%5,%5,%5,%5,%5,%5}, p;\n\t}"
        :: "r"(d), "l"(ad), "l"(bd), "r"(idesc), "r"(en), "r"(0u) : "memory");
}
static __device__ __forceinline__ void tc_commit(uint32_t mb){
    asm volatile("tcgen05.commit.cta_group::1.mbarrier::arrive::one.shared::cluster.b64 [%0];"
        :: "r"(mb) : "memory");
}
static __device__ __forceinline__ void tc_commit2_mc(uint32_t mb){
    asm volatile("tcgen05.commit.cta_group::2.mbarrier::arrive::one.shared::cluster.multicast::cluster.b64 [%0], %1;"
        :: "r"(mb), "h"((unsigned short)3) : "memory");
}
#define TC_LD32(r, ta) \
    asm volatile("tcgen05.ld.sync.aligned.32x32b.x32.b32 " \
        "{%0,%1,%2,%3,%4,%5,%6,%7,%8,%9,%10,%11,%12,%13,%14,%15," \
        "%16,%17,%18,%19,%20,%21,%22,%23,%24,%25,%26,%27,%28,%29,%30,%31}, [%32];" \
        : "=r"((r)[0]),"=r"((r)[1]),"=r"((r)[2]),"=r"((r)[3]),"=r"((r)[4]),"=r"((r)[5]), \
          "=r"((r)[6]),"=r"((r)[7]),"=r"((r)[8]),"=r"((r)[9]),"=r"((r)[10]),"=r"((r)[11]), \
          "=r"((r)[12]),"=r"((r)[13]),"=r"((r)[14]),"=r"((r)[15]),"=r"((r)[16]),"=r"((r)[17]), \
          "=r"((r)[18]),"=r"((r)[19]),"=r"((r)[20]),"=r"((r)[21]),"=r"((r)[22]),"=r"((r)[23]), \
          "=r"((r)[24]),"=r"((r)[25]),"=r"((r)[26]),"=r"((r)[27]),"=r"((r)[28]),"=r"((r)[29]), \
          "=r"((r)[30]),"=r"((r)[31]) : "r"(ta))
#define TC_ST32(ta, r) \
    asm volatile("tcgen05.st.sync.aligned.32x32b.x32.b32 [%0], " \
        "{%1,%2,%3,%4,%5,%6,%7,%8,%9,%10,%11,%12,%13,%14,%15,%16," \
        "%17,%18,%19,%20,%21,%22,%23,%24,%25,%26,%27,%28,%29,%30,%31,%32};" \
        :: "r"(ta), \
          "r"((r)[0]),"r"((r)[1]),"r"((r)[2]),"r"((r)[3]),"r"((r)[4]),"r"((r)[5]), \
          "r"((r)[6]),"r"((r)[7]),"r"((r)[8]),"r"((r)[9]),"r"((r)[10]),"r"((r)[11]), \
          "r"((r)[12]),"r"((r)[13]),"r"((r)[14]),"r"((r)[15]),"r"((r)[16]),"r"((r)[17]), \
          "r"((r)[18]),"r"((r)[19]),"r"((r)[20]),"r"((r)[21]),"r"((r)[22]),"r"((r)[23]), \
          "r"((r)[24]),"r"((r)[25]),"r"((r)[26]),"r"((r)[27]),"r"((r)[28]),"r"((r)[29]), \
          "r"((r)[30]),"r"((r)[31]) : "memory")
#endif

__global__ void embed_k(const int* __restrict__ idx, const float* __restrict__ emb,
                        float* __restrict__ x,
                        const float* __restrict__ bq, const float* __restrict__ bk,
                        const float* __restrict__ bv, float* __restrict__ bqkv) {
    int row = blockIdx.x, tok = idx[row];
    const float4* s = (const float4*)&emb[(size_t)tok*DD];
    float4* d = (float4*)&x[(size_t)row*DD];
    for (int i = threadIdx.x; i < DD/4; i += blockDim.x) d[i] = s[i];
    if (row < LL) {
        for (int i = threadIdx.x; i < DD; i += blockDim.x) {
            bqkv[row*QKVN+i]      = bq[row*DD+i];
            bqkv[row*QKVN+1024+i] = bk[row*DD+i];
            bqkv[row*QKVN+2048+i] = bv[row*DD+i];
        }
    }
}

__global__ void ln_k(const float* __restrict__ x, const float* __restrict__ w,
                     const float* __restrict__ b,
                     __nv_bfloat16* __restrict__ oh, __nv_bfloat16* __restrict__ ol) {
    int row = blockIdx.x;
    const float* xr = x + (size_t)row*DD;
    float s = 0.f, s2 = 0.f;
    for (int i = threadIdx.x; i < DD; i += 256) { float v = xr[i]; s += v; s2 += v*v; }
    __shared__ float rs[8], rs2[8];
    for (int o = 16; o > 0; o >>= 1) {
        s  += __shfl_down_sync(~0u, s, o);
        s2 += __shfl_down_sync(~0u, s2, o);
    }
    int wid = threadIdx.x>>5, lid = threadIdx.x&31;
    if (lid == 0) { rs[wid] = s; rs2[wid] = s2; }
    __syncthreads();
    if (wid == 0) {
        s = (lid<8)?rs[lid]:0.f; s2 = (lid<8)?rs2[lid]:0.f;
        for (int o = 4; o > 0; o >>= 1) {
            s  += __shfl_down_sync(~0u, s, o);
            s2 += __shfl_down_sync(~0u, s2, o);
        }
        if (lid == 0) { rs[0] = s; rs2[0] = s2; }
    }
    __syncthreads();
    float mean = rs[0]*(1.f/DD);
    float inv = rsqrtf(rs2[0]*(1.f/DD) - mean*mean + 1e-5f);
    for (int i = threadIdx.x; i < DD; i += 256) {
        float v = (xr[i]-mean)*inv*w[i] + b[i];
        __nv_bfloat16 hi, lo; split_bf16(v, hi, lo);
        oh[(size_t)row*DD+i] = hi; ol[(size_t)row*DD+i] = lo;
    }
}

__global__ void convT_k(const float* __restrict__ W, size_t srcz,
                        __nv_bfloat16* __restrict__ Wh, __nv_bfloat16* __restrict__ Wl,
                        size_t dstz, int K, int N) {
    W  += (size_t)blockIdx.z*srcz;
    Wh += (size_t)blockIdx.z*dstz;
    Wl += (size_t)blockIdx.z*dstz;
    __shared__ float t[32][33];
    int n0 = blockIdx.x*32, k0 = blockIdx.y*32;
    int tx = threadIdx.x, ty = threadIdx.y;
    for (int i = 0; i < 4; i++) {
        int n = n0 + tx;
        t[ty+i*8][tx] = (n < N) ? W[(size_t)(k0+ty+i*8)*N + n] : 0.f;
    }
    __syncthreads();
    for (int i = 0; i < 4; i++) {
        int n = n0 + ty + i*8;
        __nv_bfloat16 hi, lo; split_bf16(t[tx][ty+i*8], hi, lo);
        Wh[(size_t)n*K + k0+tx] = hi; Wl[(size_t)n*K + k0+tx] = lo;
    }
}

__global__ void convqkv3_k(const float* __restrict__ Wq, const float* __restrict__ Wk,
                           const float* __restrict__ Wv,
                           __nv_bfloat16* __restrict__ Wh, __nv_bfloat16* __restrict__ Wl) {
    int mat = blockIdx.z / LL, l = blockIdx.z % LL;
    const float* W = (mat == 0 ? Wq : mat == 1 ? Wk : Wv) + (size_t)l*DD*DD;
    size_t dof = (size_t)l*QKVN*DD + (size_t)mat*1024*DD;
    __shared__ float t[32][33];
    int n0 = blockIdx.x*32, k0 = blockIdx.y*32;
    int tx = threadIdx.x, ty = threadIdx.y;
    for (int i = 0; i < 4; i++)
        t[ty+i*8][tx] = W[(size_t)(k0+ty+i*8)*DD + n0+tx];
    __syncthreads();
    for (int i = 0; i < 4; i++) {
        int n = n0 + ty + i*8;
        __nv_bfloat16 hi, lo; split_bf16(t[tx][ty+i*8], hi, lo);
        Wh[dof + (size_t)n*DD + k0+tx] = hi; Wl[dof + (size_t)n*DD + k0+tx] = lo;
    }
}

// ------- bf16x3 GEMM: cta_group::2 (cluster pair), TMA producer -------
// per-CTA stage 64KB: Ah@0 Al@16K Bh@32K Bl@48K (B = this CTA's 128 N-rows)
// barriers: full[s]@sb+8+8s (cnt1,expect_tx) empty[s]@sb+24+8s (cnt1,mc commit)
//           peer[s]@sb+40+8s (cnt1, follower cluster-arrive; leader waits)
#define MT 128
#define NT 256
#define KT 64
#define IDESC2 ((1u<<4)|(1u<<7)|(1u<<10)|(32u<<17)|(16u<<24))   // M=256,N=256
#define STAGEB 65536
#define SMEMB (1024 + 2*STAGEB)

template<int ACT, int MODE, int RES>
__global__ void __cluster_dims__(2,1,1) __launch_bounds__(256)
tgemm_k(const __grid_constant__ CUtensorMap mapAh,
        const __grid_constant__ CUtensorMap mapAl,
        const __grid_constant__ CUtensorMap mapBh,
        const __grid_constant__ CUtensorMap mapBl,
        int zB,
        const float* __restrict__ bias, const float* __restrict__ res,
        void* __restrict__ Cv, __nv_bfloat16* __restrict__ Clo,
        __nv_bfloat16* __restrict__ Qh_, __nv_bfloat16* __restrict__ Ql_,
        __nv_bfloat16* __restrict__ Kh_, __nv_bfloat16* __restrict__ Kl_,
        __nv_bfloat16* __restrict__ Vh_, __nv_bfloat16* __restrict__ Vl_,
        int M, int N, int K)
{
#if HAS_TC
    extern __shared__ __align__(1024) char smc[];
    uint32_t sb = smem_u32(smc);
    const int tid = threadIdx.x, wid = tid>>5, lid = tid&31;
    const int rb = blockIdx.x*MT, cb = blockIdx.y*NT;
    const uint32_t rank = ctarank();
    if (wid == 0) {
        asm volatile("tcgen05.alloc.cta_group::2.sync.aligned.shared::cta.b32 [%0], %1;"
                     :: "r"(sb), "r"(256u) : "memory");
        asm volatile("tcgen05.relinquish_alloc_permit.cta_group::2.sync.aligned;");
    }
    if (tid == 0) {
        mbar_init(sb+8, 1);  mbar_init(sb+16, 1);   // full
        mbar_init(sb+24, 1); mbar_init(sb+32, 1);   // empty
        mbar_init(sb+40, 1); mbar_init(sb+48, 1);   // peer (leader-side use)
    }
    __syncthreads();
    cluster_sync();
    uint32_t tmem;
    asm volatile("ld.shared.b32 %0, [%1];" : "=r"(tmem) : "r"(sb));
    const int nk = K/KT;

    if (wid == 0) {
        if (elect_one()) {
            uint32_t eph[2] = {0, 0};
            for (int kt = 0; kt < nk; kt++) {
                const int s = kt&1;
                const uint32_t stg = sb + 1024 + s*STAGEB;
                if (kt >= 2) { mbar_wait(sb+24+s*8, eph[s]); eph[s] ^= 1; }
                mbar_expect(sb+8+s*8, STAGEB);
                tma3d(stg,       &mapAh, kt*KT, rb, 0, sb+8+s*8);
                tma3d(stg+16384, &mapAl, kt*KT, rb, 0, sb+8+s*8);
                tma3d(stg+32768, &mapBh, kt*KT, cb + (int)rank*128, zB, sb+8+s*8);
                tma3d(stg+49152, &mapBl, kt*KT, cb + (int)rank*128, zB, sb+8+s*8);
            }
        }
    } else if (wid == 7) {
        uint32_t fph[2] = {0, 0}, pph[2] = {0, 0};
        for (int kt = 0; kt < nk; kt++) {
            const int s = kt&1;
            mbar_wait(sb+8+s*8, fph[s]); fph[s] ^= 1;
            if (rank == 1) {
                if (elect_one()) mbar_arrive_rank0(sb+40+s*8);
                __syncwarp();
            } else {
                mbar_wait(sb+40+s*8, pph[s]); pph[s] ^= 1;
                if (elect_one()) {
                    const uint32_t stg = sb + 1024 + s*STAGEB;
                    uint64_t adh = mk_desc(stg), adl = mk_desc(stg+16384);
                    uint64_t bdh = mk_desc(stg+32768), bdl = mk_desc(stg+49152);
#pragma unroll
                    for (int ks = 0; ks < 4; ks++) {
                        uint32_t en = (kt>0 || ks>0) ? 1u : 0u;
                        uint64_t o = ks*2;
                        mma_f16_ss2(tmem, adh+o, bdh+o, IDESC2, en);
                        mma_f16_ss2(tmem, adh+o, bdl+o, IDESC2, 1u);
                        mma_f16_ss2(tmem, adl+o, bdh+o, IDESC2, 1u);
                    }
                    tc_commit2_mc(sb+24+s*8);
                }
                __syncwarp();
            }
        }
        const int s_last = (nk-1)&1;
        const int n_s = (nk - s_last + 1) >> 1;
        mbar_wait(sb+24+s_last*8, (uint32_t)((n_s-1)&1));
    }
    __syncthreads();
    asm volatile("tcgen05.fence::after_thread_sync;" ::: "memory");

    // coalesced epilogue: own 128 rows x 256 cols (own TMEM)
    const int sp = wid&3, nh = wid>>2;
    float* tp2 = (float*)(smc+1024) + wid*(32*33);
    float* Cf = (float*)Cv;
    __nv_bfloat16* Cb = (__nv_bfloat16*)Cv;
    for (int cc2 = 0; cc2 < 4; cc2++) {
        uint32_t r32[32];
        TC_LD32(r32, tmem + ((uint32_t)sp<<21) + nh*128 + cc2*32);
        asm volatile("tcgen05.wait::ld.sync.aligned;" ::: "memory");
        for (int j = 0; j < 32; j++) tp2[lid*33+j] = __uint_as_float(r32[j]);
        __syncwarp();
        int col = cb + nh*128 + cc2*32 + lid;
        if (MODE == 2) {
            int colb = cb + nh*128 + cc2*32;
            int sec = colb >> 10;
            int hidx = (colb >> 6) & 15;
            int dh = (colb & 63) + lid;
            int b_ = rb >> 11;
            int t0 = (rb & 2047) + sp*32;
            int bh = b_*HH + hidx;
            float bi = bias[col];
            if (sec < 2) {
                __nv_bfloat16* Dh = sec ? Kh_ : Qh_;
                __nv_bfloat16* Dl = sec ? Kl_ : Ql_;
                for (int j2 = 0; j2 < 32; j2++) {
                    float v = tp2[j2*33+lid] + bi;
                    __nv_bfloat16 hi, lo; split_bf16(v, hi, lo);
                    size_t go = ((size_t)bh*TT + t0+j2)*DH + dh;
                    Dh[go] = hi; Dl[go] = lo;
                }
            } else {
                uint4 hv[4], lv[4];
                unsigned short* hs = (unsigned short*)hv;
                unsigned short* ls = (unsigned short*)lv;
                for (int j2 = 0; j2 < 32; j2++) {
                    float v = tp2[j2*33+lid] + bi;
                    __nv_bfloat16 hi, lo; split_bf16(v, hi, lo);
                    hs[j2] = __bfloat16_as_ushort(hi);
                    ls[j2] = __bfloat16_as_ushort(lo);
                }
                size_t base = ((size_t)bh*DH + dh)*TT + t0;
                uint4* ph4 = (uint4*)(Vh_ + base);
                uint4* pl4 = (uint4*)(Vl_ + base);
                for (int q = 0; q < 4; q++) { ph4[q] = hv[q]; pl4[q] = lv[q]; }
            }
        } else if (col < N) {
            float bi = bias ? bias[col] : 0.f;
            for (int j2 = 0; j2 < 32; j2++) {
                float v = tp2[j2*33+lid] + bi;
                int row = rb + sp*32 + j2;
                if (RES) v += res[(size_t)row*N + col];
                if (ACT) v = 0.5f*v*(1.0f + erff(v*0.70710678118654752f));
                if (MODE == 1) {
                    __nv_bfloat16 hi, lo; split_bf16(v, hi, lo);
                    Cb[(size_t)row*N+col] = hi; Clo[(size_t)row*N+col] = lo;
                } else Cf[(size_t)row*N+col] = v;
            }
        }
        __syncwarp();
    }
    __syncthreads();
    if (wid == 0) {
        asm volatile("tcgen05.dealloc.cta_group::2.sync.aligned.b32 %0, %1;"
                     :: "r"(tmem), "r"(256u));
    }
    cluster_sync();
#else
    if (threadIdx.x == 0 && blockIdx.x == 0) { }   // fallback stub (cubin path runs on HW)
#endif
}

// ---------------- tcgen05 flash attention (unchanged) ----------------
#define AO_MB1 8
#define AO_MB2 16
#define AO_M   32
#define AO_L   (AO_M+512)
#define AO_AL  (AO_L+512)
#define AO_PMX (AO_AL+512)
#define AO_PSM (AO_PMX+1024)
#define AO_Q   4096
#define AO_QL  (AO_Q+16384)
#define AO_KH  (AO_QL+16384)
#define AO_KL  (AO_KH+16384)
#define AO_V0H (AO_KL+16384)
#define AO_V0L (AO_V0H+8192)
#define AO_V1H (AO_V0L+8192)
#define AO_V1L (AO_V1H+8192)
#define AO_PAH (AO_V1L+8192)
#define AO_PAL (AO_PAH+16384)
#define AO_PBH (AO_PAL+16384)
#define AO_PBL (AO_PBH+16384)
#define SMEMA  (AO_PBL+16384)
#define IDESC_S (0x490u | (16u<<17) | (8u<<24))
#define IDESC_O (0x490u | (8u<<17)  | (8u<<24))

__global__ void __launch_bounds__(256)
attn_tc_k(const __nv_bfloat16* __restrict__ Qh, const __nv_bfloat16* __restrict__ Ql,
          const __nv_bfloat16* __restrict__ Kh, const __nv_bfloat16* __restrict__ Kl,
          const __nv_bfloat16* __restrict__ Vth, const __nv_bfloat16* __restrict__ Vtl,
          __nv_bfloat16* __restrict__ yh, __nv_bfloat16* __restrict__ yl)
{
#if HAS_TC
    extern __shared__ __align__(1024) char smc[];
    uint32_t sb = smem_u32(smc);
    const int tid = threadIdx.x, wid = tid>>5, lid = tid&31;
    const int sp = wid&3, nh = wid>>2;
    const int bh = blockIdx.y, b = bh>>4, h = bh&15;
    const int qs = blockIdx.x*128;
    if (wid == 0) {
        asm volatile("tcgen05.alloc.cta_group::1.sync.aligned.shared::cta.b32 [%0], %1;"
                     :: "r"(sb), "r"(256u) : "memory");
        asm volatile("tcgen05.relinquish_alloc_permit.cta_group::1.sync.aligned;");
    }
    if (tid == 0) { mbar_init(sb+AO_MB1, 1); mbar_init(sb+AO_MB2, 1); }
    float* Mrow = (float*)(smc+AO_M);
    float* Lrow = (float*)(smc+AO_L);
    float* Arow = (float*)(smc+AO_AL);
    float* Pmax = (float*)(smc+AO_PMX);
    float* Psum = (float*)(smc+AO_PSM);
    if (tid < 128) { Mrow[tid] = -1e30f; Lrow[tid] = 0.f; }
    __syncthreads();
    uint32_t tmem;
    asm volatile("ld.shared.b32 %0, [%1];" : "=r"(tmem) : "r"(sb));
    {
        size_t qb = ((size_t)bh*TT + qs)*DH;
        for (int j = 0; j < 4; j++) {
            int i = tid + j*256, r = i>>3, u = i&7;
            int off = r*128 + u*16, sw = off ^ ((off>>3)&0x70);
            *(uint4*)(smc+AO_Q +sw) = *(const uint4*)(Qh + qb + (size_t)r*DH + u*8);
            *(uint4*)(smc+AO_QL+sw) = *(const uint4*)(Ql + qb + (size_t)r*DH + u*8);
        }
    }
    const int r = sp*32 + lid;
    const int jmax = max(qs + r, KMIN);
    const int nt = (max(qs+127, KMIN) + 128)/128;
    uint32_t ph1 = 0, ph2 = 0;
    for (int kt = 0; kt < nt; kt++) {
        int ks0 = kt*128;
        {
            size_t kb = ((size_t)bh*TT + ks0)*DH;
            for (int j = 0; j < 4; j++) {
                int i = tid + j*256, rr = i>>3, u = i&7;
                int off = rr*128 + u*16, sw = off ^ ((off>>3)&0x70);
                *(uint4*)(smc+AO_KH+sw) = *(const uint4*)(Kh + kb + (size_t)rr*DH + u*8);
                *(uint4*)(smc+AO_KL+sw) = *(const uint4*)(Kl + kb + (size_t)rr*DH + u*8);
            }
            for (int j = 0; j < 4; j++) {
                int i = tid + j*256, rr = i>>4, u = i&15;
                int off = rr*128 + (u&7)*16, sw = off ^ ((off>>3)&0x70);
                size_t src = ((size_t)bh*DH + rr)*TT + ks0 + u*8;
                int th_ = (u<8)?AO_V0H:AO_V1H, tl_ = (u<8)?AO_V0L:AO_V1L;
                *(uint4*)(smc+th_+sw) = *(const uint4*)(Vth + src);
                *(uint4*)(smc+tl_+sw) = *(const uint4*)(Vtl + src);
            }
        }
        asm volatile("fence.proxy.async.shared::cta;" ::: "memory");
        __syncthreads();
        if (wid == 0 && elect_one()) {
            uint64_t dqh = mk_desc(sb+AO_Q),  dql = mk_desc(sb+AO_QL);
            uint64_t dkh = mk_desc(sb+AO_KH), dkl = mk_desc(sb+AO_KL);
            for (int ks = 0; ks < 4; ks++) {
                uint64_t o = ks*2;
                mma_f16_ss(tmem, dqh+o, dkh+o, IDESC_S, ks>0 ? 1u:0u);
                mma_f16_ss(tmem, dqh+o, dkl+o, IDESC_S, 1u);
                mma_f16_ss(tmem, dql+o, dkh+o, IDESC_S, 1u);
            }
            tc_commit(sb+AO_MB1);
        }
        mbar_wait(sb+AO_MB1, ph1); ph1 ^= 1;
        asm volatile("tcgen05.fence::after_thread_sync;" ::: "memory");
        float s[64];
        {
            uint32_t t0[32], t1[32];
            TC_LD32(t0, tmem + ((uint32_t)sp<<21) + nh*64);
            TC_LD32(t1, tmem + ((uint32_t)sp<<21) + nh*64 + 32);
            asm volatile("tcgen05.wait::ld.sync.aligned;" ::: "memory");
            for (int j = 0; j < 32; j++) { s[j] = __uint_as_float(t0[j]); s[32+j] = __uint_as_float(t1[j]); }
        }
        float lmax = -1e30f;
        for (int j = 0; j < 64; j++) {
            int jc = ks0 + nh*64 + j;
            s[j] = (jc <= jmax) ? s[j]*0.125f : -1e30f;
            lmax = fmaxf(lmax, s[j]);
        }
        Pmax[nh*128 + r] = lmax;
        __syncthreads();
        float m_old = Mrow[r];
        float m_new = fmaxf(m_old, fmaxf(Pmax[r], Pmax[128+r]));
        float al = __expf(m_old - m_new);
        float lsum = 0.f;
        {
            int pbh = nh ? AO_PBH : AO_PAH, pbl = nh ? AO_PBL : AO_PAL;
            for (int j2 = 0; j2 < 32; j2++) {
                float p0 = __expf(s[2*j2]   - m_new);
                float p1 = __expf(s[2*j2+1] - m_new);
                lsum += p0 + p1;
                __nv_bfloat16 h0, l0, h1, l1;
                split_bf16(p0, h0, l0); split_bf16(p1, h1, l1);
                int off = r*128 + j2*4, sw = off ^ ((off>>3)&0x70);
                *(uint32_t*)(smc+pbh+sw) = ((uint32_t)__bfloat16_as_ushort(h1)<<16) | __bfloat16_as_ushort(h0);
                *(uint32_t*)(smc+pbl+sw) = ((uint32_t)__bfloat16_as_ushort(l1)<<16) | __bfloat16_as_ushort(l0);
            }
        }
        Psum[nh*128 + r] = lsum;
        if (nh == 0) Arow[r] = al;
        __syncthreads();
        if (wid < 4) { Lrow[r] = Lrow[r]*al + Psum[r] + Psum[128+r]; Mrow[r] = m_new; }
        if (kt > 0) {
            uint32_t oaddr = tmem + ((uint32_t)sp<<21) + 128 + nh*32;
            uint32_t o32[32];
            TC_LD32(o32, oaddr);
            asm volatile("tcgen05.wait::ld.sync.aligned;" ::: "memory");
            float a = Arow[r];
            for (int j = 0; j < 32; j++) o32[j] = __float_as_uint(__uint_as_float(o32[j])*a);
            TC_ST32(oaddr, o32);
            asm volatile("tcgen05.wait::st.sync.aligned;" ::: "memory");
        }
        asm volatile("tcgen05.fence::before_thread_sync;" ::: "memory");
        asm volatile("fence.proxy.async.shared::cta;" ::: "memory");
        __syncthreads();
        if (wid == 0 && elect_one()) {
            asm volatile("tcgen05.fence::after_thread_sync;" ::: "memory");
            uint64_t dp[4] = { mk_desc(sb+AO_PAH), mk_desc(sb+AO_PBH),
                               mk_desc(sb+AO_PAL), mk_desc(sb+AO_PBL) };
            uint64_t dv[4] = { mk_desc(sb+AO_V0H), mk_desc(sb+AO_V1H),
                               mk_desc(sb+AO_V0L), mk_desc(sb+AO_V1L) };
            for (int ks = 0; ks < 8; ks++) {
                int g = ks>>2;
                uint64_t o = (uint64_t)(ks&3)*2;
                uint32_t en = (kt==0 && ks==0) ? 0u : 1u;
                mma_f16_ss(tmem+128, dp[g]+o,   dv[g]+o,   IDESC_O, en);
                mma_f16_ss(tmem+128, dp[g]+o,   dv[g+2]+o, IDESC_O, 1u);
                mma_f16_ss(tmem+128, dp[g+2]+o, dv[g]+o,   IDESC_O, 1u);
            }
            tc_commit(sb+AO_MB2);
        }
        mbar_wait(sb+AO_MB2, ph2); ph2 ^= 1;
        asm volatile("tcgen05.fence::after_thread_sync;" ::: "memory");
        __syncthreads();
    }
    {
        uint32_t o32[32];
        TC_LD32(o32, tmem + ((uint32_t)sp<<21) + 128 + nh*32);
        asm volatile("tcgen05.wait::ld.sync.aligned;" ::: "memory");
        float linv = 1.f/Lrow[r];
        float* tp = (float*)(smc+AO_PAH) + wid*(32*33);
        for (int j = 0; j < 32; j++) tp[lid*33+j] = __uint_as_float(o32[j])*linv;
        __syncwarp();
        for (int j2 = 0; j2 < 32; j2++) {
            float v = tp[j2*33+lid];
            int grow = qs + sp*32 + j2;
            int gcol = h*DH + nh*32 + lid;
            __nv_bfloat16 hi, lo; split_bf16(v, hi, lo);
            size_t go = ((size_t)b*TT + grow)*DD + gcol;
            yh[go] = hi; yl[go] = lo;
        }
    }
    __syncthreads();
    if (wid == 0)
        asm volatile("tcgen05.dealloc.cta_group::1.sync.aligned.b32 %0, %1;"
                     :: "r"(tmem), "r"(256u));
#else
    int bh = blockIdx.y, b = bh>>4, h = bh&15;
    if (threadIdx.x >= 128) return;
    int qi = blockIdx.x*128 + threadIdx.x;
    float q[DH], o[DH];
    size_t qb = ((size_t)bh*TT + qi)*DH;
    for (int d = 0; d < DH; d++) {
        q[d] = __bfloat162float(Qh[qb+d]) + __bfloat162float(Ql[qb+d]); o[d] = 0.f;
    }
    float m = -1e30f, l = 0.f;
    int jm = max(qi, KMIN);
    for (int j = 0; j <= jm; j++) {
        size_t kb = ((size_t)bh*TT + j)*DH;
        float s = 0.f;
        for (int d = 0; d < DH; d++)
            s += q[d]*(__bfloat162float(Kh[kb+d]) + __bfloat162float(Kl[kb+d]));
        s *= 0.125f;
        float mn = fmaxf(m, s), al = __expf(m-mn), p = __expf(s-mn);
        l = l*al + p;
        for (int d = 0; d < DH; d++) {
            size_t vo = ((size_t)bh*DH + d)*TT + j;
            o[d] = o[d]*al + p*(__bfloat162float(Vth[vo]) + __bfloat162float(Vtl[vo]));
        }
        m = mn;
    }
    for (int d = 0; d < DH; d++) {
        __nv_bfloat16 hi, lo; split_bf16(o[d]/l, hi, lo);
        size_t go = ((size_t)b*TT + qi)*DD + h*DH + d;
        yh[go] = hi; yl[go] = lo;
    }
#endif
}

// ---------------- host ----------------
typedef CUresult (*tmap_fn_t)(CUtensorMap*, CUtensorMapDataType, cuuint32_t, void*,
                              const cuuint64_t*, const cuuint64_t*, const cuuint32_t*,
                              const cuuint32_t*, CUtensorMapInterleave, CUtensorMapSwizzle,
                              CUtensorMapL2promotion, CUtensorMapFloatOOBfill);

static void mk_map(tmap_fn_t fn, CUtensorMap* m, void* p,
                   uint64_t d0, uint64_t d1, uint64_t d2, uint32_t box1) {
    cuuint64_t dims[3] = {d0, d1, d2};
    cuuint64_t strides[2] = {d0*2, d0*d1*2};
    cuuint32_t box[3] = {64, box1, 1};
    cuuint32_t es[3] = {1, 1, 1};
    fn(m, CU_TENSOR_MAP_DATA_TYPE_BFLOAT16, 3, p, dims, strides, box, es,
       CU_TENSOR_MAP_INTERLEAVE_NONE, CU_TENSOR_MAP_SWIZZLE_128B,
       CU_TENSOR_MAP_L2_PROMOTION_L2_128B, CU_TENSOR_MAP_FLOAT_OOB_FILL_NONE);
}

extern "C" void kernel_launch(void* const* d_in, const int* in_sizes, int n_in,
                              void* d_out, int out_size) {
    const int*   idx     = (const int*)  d_in[0];
    const float* tok_emb = (const float*)d_in[1];
    const float* ln1_w = (const float*)d_in[2],  *ln1_b = (const float*)d_in[3];
    const float* Wq = (const float*)d_in[4],  *bq = (const float*)d_in[5];
    const float* Wk = (const float*)d_in[6],  *bk = (const float*)d_in[7];
    const float* Wv = (const float*)d_in[8],  *bv = (const float*)d_in[9];
    const float* Wp = (const float*)d_in[10], *bp = (const float*)d_in[11];
    const float* ln2_w = (const float*)d_in[12], *ln2_b = (const float*)d_in[13];
    const float* W1 = (const float*)d_in[14], *b1 = (const float*)d_in[15];
    const float* W2 = (const float*)d_in[16], *b2 = (const float*)d_in[17];
    const float* lnf_w = (const float*)d_in[18], *lnf_b = (const float*)d_in[19];
    const float* head_w = (const float*)d_in[20];
    float* out = (float*)d_out;

    float *x, *bqkv;
    __nv_bfloat16 *hh,*hl,*yh,*yl,*m1h,*m1l,*qah,*qal,*kah,*kal,*vth,*vtl;
    __nv_bfloat16 *wqkvh,*wqkvl,*wph,*wpl,*w1h,*w1l,*w2h,*w2l,*whh,*whl;
    cudaGetSymbolAddress((void**)&x, g_x);
    cudaGetSymbolAddress((void**)&hh, g_hh);   cudaGetSymbolAddress((void**)&hl, g_hl);
    cudaGetSymbolAddress((void**)&yh, g_yh);   cudaGetSymbolAddress((void**)&yl, g_yl);
    cudaGetSymbolAddress((void**)&m1h, g_m1h); cudaGetSymbolAddress((void**)&m1l, g_m1l);
    cudaGetSymbolAddress((void**)&qah, g_qah); cudaGetSymbolAddress((void**)&qal, g_qal);
    cudaGetSymbolAddress((void**)&kah, g_kah); cudaGetSymbolAddress((void**)&kal, g_kal);
    cudaGetSymbolAddress((void**)&vth, g_vth); cudaGetSymbolAddress((void**)&vtl, g_vtl);
    cudaGetSymbolAddress((void**)&wqkvh, g_wqkvh); cudaGetSymbolAddress((void**)&wqkvl, g_wqkvl);
    cudaGetSymbolAddress((void**)&wph, g_wph); cudaGetSymbolAddress((void**)&wpl, g_wpl);
    cudaGetSymbolAddress((void**)&w1h, g_w1h); cudaGetSymbolAddress((void**)&w1l, g_w1l);
    cudaGetSymbolAddress((void**)&w2h, g_w2h); cudaGetSymbolAddress((void**)&w2l, g_w2l);
    cudaGetSymbolAddress((void**)&whh, g_whh); cudaGetSymbolAddress((void**)&whl, g_whl);
    cudaGetSymbolAddress((void**)&bqkv, g_bqkv);

    static tmap_fn_t fn = nullptr;
    if (!fn) {
        cudaDriverEntryPointQueryResult st;
        cudaGetDriverEntryPoint("cuTensorMapEncodeTiled", (void**)&fn,
                                cudaEnableDefault, &st);
    }
    static CUtensorMap mAh, mAl, mYh, mYl, mMh, mMl;
    static CUtensorMap mQKVh, mQKVl, mPh, mPl, mW1h, mW1l, mW2h, mW2l, mHh, mHl;
    mk_map(fn, &mAh, hh, DD, MM_, 1, 128);   mk_map(fn, &mAl, hl, DD, MM_, 1, 128);
    mk_map(fn, &mYh, yh, DD, MM_, 1, 128);   mk_map(fn, &mYl, yl, DD, MM_, 1, 128);
    mk_map(fn, &mMh, m1h, FF, MM_, 1, 128);  mk_map(fn, &mMl, m1l, FF, MM_, 1, 128);
    mk_map(fn, &mQKVh, wqkvh, DD, QKVN, LL, 128); mk_map(fn, &mQKVl, wqkvl, DD, QKVN, LL, 128);
    mk_map(fn, &mPh, wph, DD, DD, LL, 128);  mk_map(fn, &mPl, wpl, DD, DD, LL, 128);
    mk_map(fn, &mW1h, w1h, DD, FF, LL, 128); mk_map(fn, &mW1l, w1l, DD, FF, LL, 128);
    mk_map(fn, &mW2h, w2h, FF, DD, LL, 128); mk_map(fn, &mW2l, w2l, FF, DD, LL, 128);
    mk_map(fn, &mHh, whh, DD, VPAD, 1, 128); mk_map(fn, &mHl, whl, DD, VPAD, 1, 128);

    cudaFuncSetAttribute(tgemm_k<0,0,0>, cudaFuncAttributeMaxDynamicSharedMemorySize, SMEMB);
    cudaFuncSetAttribute(tgemm_k<0,0,1>, cudaFuncAttributeMaxDynamicSharedMemorySize, SMEMB);
    cudaFuncSetAttribute(tgemm_k<1,1,0>, cudaFuncAttributeMaxDynamicSharedMemorySize, SMEMB);
    cudaFuncSetAttribute(tgemm_k<0,2,0>, cudaFuncAttributeMaxDynamicSharedMemorySize, SMEMB);
    cudaFuncSetAttribute(attn_tc_k, cudaFuncAttributeMaxDynamicSharedMemorySize, SMEMA);

    dim3 tb(32, 8);
    dim3 gQKV (MM_/MT, QKVN/NT), gPROJ(MM_/MT, DD/NT);
    dim3 gMLP1(MM_/MT, FF/NT),   gHEAD(MM_/MT, VPAD/NT);
    dim3 gAtt (TT/128, BB*HH);

    convqkv3_k<<<dim3(DD/32, DD/32, 3*LL), tb>>>(Wq, Wk, Wv, wqkvh, wqkvl);
    embed_k<<<MM_, 256>>>(idx, tok_emb, x, bq, bk, bv, bqkv);
    ln_k<<<MM_, 256>>>(x, ln1_w, ln1_b, hh, hl);
    tgemm_k<0,2,0><<<gQKV, 256, SMEMB>>>(mAh, mAl, mQKVh, mQKVl, 0,
        bqkv, nullptr, nullptr, nullptr, qah, qal, kah, kal, vth, vtl, MM_, QKVN, DD);
    convT_k<<<dim3(DD/32, DD/32, LL), tb>>>(Wp, (size_t)DD*DD, wph, wpl, (size_t)DD*DD, DD, DD);
    convT_k<<<dim3(FF/32, DD/32, LL), tb>>>(W1, (size_t)DD*FF, w1h, w1l, (size_t)DD*FF, DD, FF);
    convT_k<<<dim3(DD/32, FF/32, LL), tb>>>(W2, (size_t)DD*FF, w2h, w2l, (size_t)DD*FF, FF, DD);
    convT_k<<<dim3(VPAD/32, DD/32, 1), tb>>>(head_w, 0, whh, whl, 0, DD, VV);

    for (int l = 0; l < LL; l++) {
        size_t oD = (size_t)l*DD;
        if (l > 0) {
            ln_k<<<MM_, 256>>>(x, ln1_w+oD, ln1_b+oD, hh, hl);
            tgemm_k<0,2,0><<<gQKV, 256, SMEMB>>>(mAh, mAl, mQKVh, mQKVl, l,
                bqkv+l*QKVN, nullptr, nullptr, nullptr, qah, qal, kah, kal, vth, vtl,
                MM_, QKVN, DD);
        }
        attn_tc_k<<<gAtt, 256, SMEMA>>>(qah, qal, kah, kal, vth, vtl, yh, yl);
        tgemm_k<0,0,1><<<gPROJ, 256, SMEMB>>>(mYh, mYl, mPh, mPl, l,
            bp+oD, x, x, nullptr, nullptr, nullptr, nullptr, nullptr, nullptr, nullptr,
            MM_, DD, DD);
        ln_k<<<MM_, 256>>>(x, ln2_w+oD, ln2_b+oD, hh, hl);
        tgemm_k<1,1,0><<<gMLP1, 256, SMEMB>>>(mAh, mAl, mW1h, mW1l, l,
            b1+(size_t)l*FF, nullptr, m1h, m1l, nullptr, nullptr, nullptr, nullptr, nullptr, nullptr,
            MM_, FF, DD);
        tgemm_k<0,0,1><<<gPROJ, 256, SMEMB>>>(mMh, mMl, mW2h, mW2l, l,
            b2+oD, x, x, nullptr, nullptr, nullptr, nullptr, nullptr, nullptr, nullptr,
            MM_, DD, FF);
    }
    ln_k<<<MM_, 256>>>(x, lnf_w, lnf_b, hh, hl);
    tgemm_k<0,0,0><<<gHEAD, 256, SMEMB>>>(mAh, mAl, mHh, mHl, 0,
        nullptr, nullptr, out, nullptr, nullptr, nullptr, nullptr, nullptr, nullptr, nullptr,
        MM_, VV, DD);
}

// round 16
// speedup vs baseline: 1.0428x; 1.0428x over previous
#include <cuda_runtime.h>
#include <cuda.h>
#include <cuda_bf16.h>
#include <math.h>
#include <stdint.h>

#define BB 2
#define TT 2048
#define DD 1024
#define HH 16
#define DH 64
#define LL 6
#define VV 50257
#define FF 4096
#define MM_ (BB*TT)
#define KMIN (TT-512)
#define VPAD 50432
#define QKVN 3072

#if !defined(__CUDA_ARCH__) || defined(__CUDA_ARCH_FEAT_SM103_ALL) || defined(__CUDA_ARCH_FEAT_SM100_ALL)
#define HAS_TC 1
#else
#define HAS_TC 0
#endif

__device__ float         g_x  [MM_*DD];
__device__ __nv_bfloat16 g_hh [MM_*DD];
__device__ __nv_bfloat16 g_hl [MM_*DD];
__device__ __nv_bfloat16 g_yh [MM_*DD];
__device__ __nv_bfloat16 g_yl [MM_*DD];
__device__ __nv_bfloat16 g_m1h[(size_t)MM_*FF];
__device__ __nv_bfloat16 g_m1l[(size_t)MM_*FF];
__device__ __nv_bfloat16 g_qah[BB*HH*TT*DH];
__device__ __nv_bfloat16 g_qal[BB*HH*TT*DH];
__device__ __nv_bfloat16 g_kah[BB*HH*TT*DH];
__device__ __nv_bfloat16 g_kal[BB*HH*TT*DH];
__device__ __nv_bfloat16 g_vth[BB*HH*TT*DH];
__device__ __nv_bfloat16 g_vtl[BB*HH*TT*DH];
__device__ __nv_bfloat16 g_wqkvh[(size_t)LL*QKVN*DD];
__device__ __nv_bfloat16 g_wqkvl[(size_t)LL*QKVN*DD];
__device__ __nv_bfloat16 g_wph[(size_t)LL*DD*DD];
__device__ __nv_bfloat16 g_wpl[(size_t)LL*DD*DD];
__device__ __nv_bfloat16 g_w1h[(size_t)LL*FF*DD];
__device__ __nv_bfloat16 g_w1l[(size_t)LL*FF*DD];
__device__ __nv_bfloat16 g_w2h[(size_t)LL*DD*FF];
__device__ __nv_bfloat16 g_w2l[(size_t)LL*DD*FF];
__device__ __nv_bfloat16 g_whh[(size_t)VPAD*DD];
__device__ __nv_bfloat16 g_whl[(size_t)VPAD*DD];
__device__ float         g_bqkv[LL*QKVN];

static __device__ __forceinline__ uint32_t smem_u32(const void* p){
    uint32_t a;
    asm("{ .reg .u64 t; cvta.to.shared.u64 t, %1; cvt.u32.u64 %0, t; }":"=r"(a):"l"(p));
    return a;
}
static __device__ __forceinline__ void split_bf16(float v, __nv_bfloat16& hi, __nv_bfloat16& lo){
    hi = __float2bfloat16(v);
    lo = __float2bfloat16(v - __bfloat162float(hi));
}
#if HAS_TC
static __device__ __forceinline__ uint32_t elect_one(){
    uint32_t r;
    asm volatile("{ .reg .pred p; elect.sync _|p, 0xFFFFFFFF; selp.b32 %0,1,0,p; }":"=r"(r));
    return r;
}
static __device__ __forceinline__ uint32_t ctarank(){
    uint32_t r; asm("mov.u32 %0, %%cluster_ctarank;" : "=r"(r)); return r;
}
static __device__ __forceinline__ void cluster_sync(){
    asm volatile("barrier.cluster.arrive.aligned;" ::: "memory");
    asm volatile("barrier.cluster.wait.aligned;" ::: "memory");
}
static __device__ __forceinline__ void mbar_init(uint32_t a, uint32_t c){
    asm volatile("mbarrier.init.shared.b64 [%0], %1;" :: "r"(a), "r"(c) : "memory");
}
static __device__ __forceinline__ void mbar_wait(uint32_t a, uint32_t ph){
    asm volatile("{\n\t.reg .pred P;\nWL_%=:\n\t"
        "mbarrier.try_wait.parity.acquire.cta.shared::cta.b64 P, [%0], %1;\n\t"
        "@!P bra WL_%=;\n\t}" :: "r"(a), "r"(ph) : "memory");
}
static __device__ __forceinline__ void mbar_expect(uint32_t a, uint32_t bytes){
    asm volatile("mbarrier.arrive.expect_tx.shared.b64 _, [%0], %1;"
                 :: "r"(a), "r"(bytes) : "memory");
}
static __device__ __forceinline__ void mbar_arrive_rank0(uint32_t a){
    asm volatile("{\n\t.reg .b32 ra;\n\tmapa.shared::cluster.u32 ra, %0, 0;\n\t"
        "mbarrier.arrive.shared::cluster.b64 _, [ra];\n\t}" :: "r"(a) : "memory");
}
static __device__ __forceinline__ void tma3d(uint32_t smem, const void* map,
                                             int x, int y, int z, uint32_t mbar){
    asm volatile("cp.async.bulk.tensor.3d.shared::cta.global.tile.mbarrier::complete_tx::bytes "
        "[%0], [%1, {%2, %3, %4}], [%5];"
        :: "r"(smem), "l"(map), "r"(x), "r"(y), "r"(z), "r"(mbar) : "memory");
}
static __device__ __forceinline__ uint64_t mk_desc(uint32_t addr){
    return (uint64_t(2)<<61)|(uint64_t(1)<<46)|(uint64_t(64)<<32)|(uint64_t(1)<<16)
         |((uint64_t)(addr>>4)&0x3FFF);
}
static __device__ __forceinline__ void mma_f16_ss(uint32_t d, uint64_t ad, uint64_t bd,
                                                  uint32_t idesc, uint32_t en){
    asm volatile("{\n\t.reg .pred p;\n\tsetp.ne.u32 p, %4, 0;\n\t"
        "tcgen05.mma.cta_group::1.kind::f16 [%0], %1, %2, %3, {%5,%5,%5,%5}, p;\n\t}"
        :: "r"(d), "l"(ad), "l"(bd), "r"(idesc), "r"(en), "r"(0u) : "memory");
}
static __device__ __forceinline__ void mma_f16_ss2(uint32_t d, uint64_t ad, uint64_t bd,
                                                   uint32_t idesc, uint32_t en){
    asm volatile("{\n\t.reg .pred p;\n\tsetp.ne.u32 p, %4, 0;\n\t"
        "tcgen05.mma.cta_group::2.kind::f16 [%0], %1, %2, %3, {%5,%5,%5,%5,%5,%5,%5,%5}, p;\n\t}"
        :: "r"(d), "l"(ad), "l"(bd), "r"(idesc), "r"(en), "r"(0u) : "memory");
}
static __device__ __forceinline__ void tc_commit(uint32_t mb){
    asm volatile("tcgen05.commit.cta_group::1.mbarrier::arrive::one.shared::cluster.b64 [%0];"
        :: "r"(mb) : "memory");
}
static __device__ __forceinline__ void tc_commit2_mc(uint32_t mb){
    asm volatile("tcgen05.commit.cta_group::2.mbarrier::arrive::one.shared::cluster.multicast::cluster.b64 [%0], %1;"
        :: "r"(mb), "h"((unsigned short)3) : "memory");
}
#define TC_LD32(r, ta) \
    asm volatile("tcgen05.ld.sync.aligned.32x32b.x32.b32 " \
        "{%0,%1,%2,%3,%4,%5,%6,%7,%8,%9,%10,%11,%12,%13,%14,%15," \
        "%16,%17,%18,%19,%20,%21,%22,%23,%24,%25,%26,%27,%28,%29,%30,%31}, [%32];" \
        : "=r"((r)[0]),"=r"((r)[1]),"=r"((r)[2]),"=r"((r)[3]),"=r"((r)[4]),"=r"((r)[5]), \
          "=r"((r)[6]),"=r"((r)[7]),"=r"((r)[8]),"=r"((r)[9]),"=r"((r)[10]),"=r"((r)[11]), \
          "=r"((r)[12]),"=r"((r)[13]),"=r"((r)[14]),"=r"((r)[15]),"=r"((r)[16]),"=r"((r)[17]), \
          "=r"((r)[18]),"=r"((r)[19]),"=r"((r)[20]),"=r"((r)[21]),"=r"((r)[22]),"=r"((r)[23]), \
          "=r"((r)[24]),"=r"((r)[25]),"=r"((r)[26]),"=r"((r)[27]),"=r"((r)[28]),"=r"((r)[29]), \
          "=r"((r)[30]),"=r"((r)[31]) : "r"(ta))
#define TC_ST32(ta, r) \
    asm volatile("tcgen05.st.sync.aligned.32x32b.x32.b32 [%0], " \
        "{%1,%2,%3,%4,%5,%6,%7,%8,%9,%10,%11,%12,%13,%14,%15,%16," \
        "%17,%18,%19,%20,%21,%22,%23,%24,%25,%26,%27,%28,%29,%30,%31,%32};" \
        :: "r"(ta), \
          "r"((r)[0]),"r"((r)[1]),"r"((r)[2]),"r"((r)[3]),"r"((r)[4]),"r"((r)[5]), \
          "r"((r)[6]),"r"((r)[7]),"r"((r)[8]),"r"((r)[9]),"r"((r)[10]),"r"((r)[11]), \
          "r"((r)[12]),"r"((r)[13]),"r"((r)[14]),"r"((r)[15]),"r"((r)[16]),"r"((r)[17]), \
          "r"((r)[18]),"r"((r)[19]),"r"((r)[20]),"r"((r)[21]),"r"((r)[22]),"r"((r)[23]), \
          "r"((r)[24]),"r"((r)[25]),"r"((r)[26]),"r"((r)[27]),"r"((r)[28]),"r"((r)[29]), \
          "r"((r)[30]),"r"((r)[31]) : "memory")
#endif

__global__ void embed_k(const int* __restrict__ idx, const float* __restrict__ emb,
                        float* __restrict__ x,
                        const float* __restrict__ bq, const float* __restrict__ bk,
                        const float* __restrict__ bv, float* __restrict__ bqkv) {
    int row = blockIdx.x, tok = idx[row];
    const float4* s = (const float4*)&emb[(size_t)tok*DD];
    float4* d = (float4*)&x[(size_t)row*DD];
    for (int i = threadIdx.x; i < DD/4; i += blockDim.x) d[i] = s[i];
    if (row < LL) {
        for (int i = threadIdx.x; i < DD; i += blockDim.x) {
            bqkv[row*QKVN+i]      = bq[row*DD+i];
            bqkv[row*QKVN+1024+i] = bk[row*DD+i];
            bqkv[row*QKVN+2048+i] = bv[row*DD+i];
        }
    }
}

__global__ void ln_k(const float* __restrict__ x, const float* __restrict__ w,
                     const float* __restrict__ b,
                     __nv_bfloat16* __restrict__ oh, __nv_bfloat16* __restrict__ ol) {
    int row = blockIdx.x;
    const float* xr = x + (size_t)row*DD;
    float s = 0.f, s2 = 0.f;
    for (int i = threadIdx.x; i < DD; i += 256) { float v = xr[i]; s += v; s2 += v*v; }
    __shared__ float rs[8], rs2[8];
    for (int o = 16; o > 0; o >>= 1) {
        s  += __shfl_down_sync(~0u, s, o);
        s2 += __shfl_down_sync(~0u, s2, o);
    }
    int wid = threadIdx.x>>5, lid = threadIdx.x&31;
    if (lid == 0) { rs[wid] = s; rs2[wid] = s2; }
    __syncthreads();
    if (wid == 0) {
        s = (lid<8)?rs[lid]:0.f; s2 = (lid<8)?rs2[lid]:0.f;
        for (int o = 4; o > 0; o >>= 1) {
            s  += __shfl_down_sync(~0u, s, o);
            s2 += __shfl_down_sync(~0u, s2, o);
        }
        if (lid == 0) { rs[0] = s; rs2[0] = s2; }
    }
    __syncthreads();
    float mean = rs[0]*(1.f/DD);
    float inv = rsqrtf(rs2[0]*(1.f/DD) - mean*mean + 1e-5f);
    for (int i = threadIdx.x; i < DD; i += 256) {
        float v = (xr[i]-mean)*inv*w[i] + b[i];
        __nv_bfloat16 hi, lo; split_bf16(v, hi, lo);
        oh[(size_t)row*DD+i] = hi; ol[(size_t)row*DD+i] = lo;
    }
}

__global__ void convT_k(const float* __restrict__ W, size_t srcz,
                        __nv_bfloat16* __restrict__ Wh, __nv_bfloat16* __restrict__ Wl,
                        size_t dstz, int K, int N) {
    W  += (size_t)blockIdx.z*srcz;
    Wh += (size_t)blockIdx.z*dstz;
    Wl += (size_t)blockIdx.z*dstz;
    __shared__ float t[32][33];
    int n0 = blockIdx.x*32, k0 = blockIdx.y*32;
    int tx = threadIdx.x, ty = threadIdx.y;
    for (int i = 0; i < 4; i++) {
        int n = n0 + tx;
        t[ty+i*8][tx] = (n < N) ? W[(size_t)(k0+ty+i*8)*N + n] : 0.f;
    }
    __syncthreads();
    for (int i = 0; i < 4; i++) {
        int n = n0 + ty + i*8;
        __nv_bfloat16 hi, lo; split_bf16(t[tx][ty+i*8], hi, lo);
        Wh[(size_t)n*K + k0+tx] = hi; Wl[(size_t)n*K + k0+tx] = lo;
    }
}

__global__ void convqkv3_k(const float* __restrict__ Wq, const float* __restrict__ Wk,
                           const float* __restrict__ Wv,
                           __nv_bfloat16* __restrict__ Wh, __nv_bfloat16* __restrict__ Wl) {
    int mat = blockIdx.z / LL, l = blockIdx.z % LL;
    const float* W = (mat == 0 ? Wq : mat == 1 ? Wk : Wv) + (size_t)l*DD*DD;
    size_t dof = (size_t)l*QKVN*DD + (size_t)mat*1024*DD;
    __shared__ float t[32][33];
    int n0 = blockIdx.x*32, k0 = blockIdx.y*32;
    int tx = threadIdx.x, ty = threadIdx.y;
    for (int i = 0; i < 4; i++)
        t[ty+i*8][tx] = W[(size_t)(k0+ty+i*8)*DD + n0+tx];
    __syncthreads();
    for (int i = 0; i < 4; i++) {
        int n = n0 + ty + i*8;
        __nv_bfloat16 hi, lo; split_bf16(t[tx][ty+i*8], hi, lo);
        Wh[dof + (size_t)n*DD + k0+tx] = hi; Wl[dof + (size_t)n*DD + k0+tx] = lo;
    }
}

// ------- bf16x3 GEMM: cta_group::2, TMA producer, 3-stage pipeline -------
// per-CTA stage 64KB: Ah@0 Al@16K Bh@32K Bl@48K (B = this CTA's 128 N-rows)
// full[s]@sb+8+8s  empty[s]@sb+32+8s  peer[s]@sb+56+8s   (s=0..2)
#define MT 128
#define NT 256
#define KT 64
#define NST 3
#define IDESC2 ((1u<<4)|(1u<<7)|(1u<<10)|(32u<<17)|(16u<<24))   // M=256,N=256
#define STAGEB 65536
#define SMEMB (1024 + NST*STAGEB)

template<int ACT, int MODE, int RES>
__global__ void __cluster_dims__(2,1,1) __launch_bounds__(256)
tgemm_k(const __grid_constant__ CUtensorMap mapAh,
        const __grid_constant__ CUtensorMap mapAl,
        const __grid_constant__ CUtensorMap mapBh,
        const __grid_constant__ CUtensorMap mapBl,
        int zB,
        const float* __restrict__ bias, const float* __restrict__ res,
        void* __restrict__ Cv, __nv_bfloat16* __restrict__ Clo,
        __nv_bfloat16* __restrict__ Qh_, __nv_bfloat16* __restrict__ Ql_,
        __nv_bfloat16* __restrict__ Kh_, __nv_bfloat16* __restrict__ Kl_,
        __nv_bfloat16* __restrict__ Vh_, __nv_bfloat16* __restrict__ Vl_,
        int M, int N, int K)
{
#if HAS_TC
    extern __shared__ __align__(1024) char smc[];
    uint32_t sb = smem_u32(smc);
    const int tid = threadIdx.x, wid = tid>>5, lid = tid&31;
    const int rb = blockIdx.x*MT, cb = blockIdx.y*NT;
    const uint32_t rank = ctarank();
    if (wid == 0) {
        asm volatile("tcgen05.alloc.cta_group::2.sync.aligned.shared::cta.b32 [%0], %1;"
                     :: "r"(sb), "r"(256u) : "memory");
        asm volatile("tcgen05.relinquish_alloc_permit.cta_group::2.sync.aligned;");
    }
    if (tid == 0) {
        for (int s = 0; s < NST; s++) {
            mbar_init(sb+8+s*8, 1);    // full
            mbar_init(sb+32+s*8, 1);   // empty
            mbar_init(sb+56+s*8, 1);   // peer
        }
    }
    __syncthreads();
    cluster_sync();
    uint32_t tmem;
    asm volatile("ld.shared.b32 %0, [%1];" : "=r"(tmem) : "r"(sb));
    const int nk = K/KT;

    if (wid == 0) {
        if (elect_one()) {
            uint32_t eph[NST] = {0, 0, 0};
            int s = 0;
            for (int kt = 0; kt < nk; kt++) {
                const uint32_t stg = sb + 1024 + s*STAGEB;
                if (kt >= NST) { mbar_wait(sb+32+s*8, eph[s]); eph[s] ^= 1; }
                mbar_expect(sb+8+s*8, STAGEB);
                tma3d(stg,       &mapAh, kt*KT, rb, 0, sb+8+s*8);
                tma3d(stg+16384, &mapAl, kt*KT, rb, 0, sb+8+s*8);
                tma3d(stg+32768, &mapBh, kt*KT, cb + (int)rank*128, zB, sb+8+s*8);
                tma3d(stg+49152, &mapBl, kt*KT, cb + (int)rank*128, zB, sb+8+s*8);
                if (++s == NST) s = 0;
            }
        }
    } else if (wid == 7) {
        uint32_t fph[NST] = {0, 0, 0}, pph[NST] = {0, 0, 0};
        int s = 0;
        for (int kt = 0; kt < nk; kt++) {
            mbar_wait(sb+8+s*8, fph[s]); fph[s] ^= 1;
            if (rank == 1) {
                if (elect_one()) mbar_arrive_rank0(sb+56+s*8);
                __syncwarp();
            } else {
                mbar_wait(sb+56+s*8, pph[s]); pph[s] ^= 1;
                if (elect_one()) {
                    const uint32_t stg = sb + 1024 + s*STAGEB;
                    uint64_t adh = mk_desc(stg), adl = mk_desc(stg+16384);
                    uint64_t bdh = mk_desc(stg+32768), bdl = mk_desc(stg+49152);
#pragma unroll
                    for (int ks = 0; ks < 4; ks++) {
                        uint32_t en = (kt>0 || ks>0) ? 1u : 0u;
                        uint64_t o = ks*2;
                        mma_f16_ss2(tmem, adh+o, bdh+o, IDESC2, en);
                        mma_f16_ss2(tmem, adh+o, bdl+o, IDESC2, 1u);
                        mma_f16_ss2(tmem, adl+o, bdh+o, IDESC2, 1u);
                    }
                    tc_commit2_mc(sb+32+s*8);
                }
                __syncwarp();
            }
            if (++s == NST) s = 0;
        }
        const int s_last = (nk-1) % NST;
        const int uses = (nk-1-s_last)/NST + 1;
        mbar_wait(sb+32+s_last*8, (uint32_t)((uses-1)&1));
    }
    __syncthreads();
    asm volatile("tcgen05.fence::after_thread_sync;" ::: "memory");

    // coalesced epilogue: own 128 rows x 256 cols (own TMEM)
    const int sp = wid&3, nh = wid>>2;
    float* tp2 = (float*)(smc+1024) + wid*(32*33);
    float* Cf = (float*)Cv;
    __nv_bfloat16* Cb = (__nv_bfloat16*)Cv;
    for (int cc2 = 0; cc2 < 4; cc2++) {
        uint32_t r32[32];
        TC_LD32(r32, tmem + ((uint32_t)sp<<21) + nh*128 + cc2*32);
        asm volatile("tcgen05.wait::ld.sync.aligned;" ::: "memory");
        for (int j = 0; j < 32; j++) tp2[lid*33+j] = __uint_as_float(r32[j]);
        __syncwarp();
        int col = cb + nh*128 + cc2*32 + lid;
        if (MODE == 2) {
            int colb = cb + nh*128 + cc2*32;
            int sec = colb >> 10;
            int hidx = (colb >> 6) & 15;
            int dh = (colb & 63) + lid;
            int b_ = rb >> 11;
            int t0 = (rb & 2047) + sp*32;
            int bh = b_*HH + hidx;
            float bi = bias[col];
            if (sec < 2) {
                __nv_bfloat16* Dh = sec ? Kh_ : Qh_;
                __nv_bfloat16* Dl = sec ? Kl_ : Ql_;
                for (int j2 = 0; j2 < 32; j2++) {
                    float v = tp2[j2*33+lid] + bi;
                    __nv_bfloat16 hi, lo; split_bf16(v, hi, lo);
                    size_t go = ((size_t)bh*TT + t0+j2)*DH + dh;
                    Dh[go] = hi; Dl[go] = lo;
                }
            } else {
                uint4 hv[4], lv[4];
                unsigned short* hs = (unsigned short*)hv;
                unsigned short* ls = (unsigned short*)lv;
                for (int j2 = 0; j2 < 32; j2++) {
                    float v = tp2[j2*33+lid] + bi;
                    __nv_bfloat16 hi, lo; split_bf16(v, hi, lo);
                    hs[j2] = __bfloat16_as_ushort(hi);
                    ls[j2] = __bfloat16_as_ushort(lo);
                }
                size_t base = ((size_t)bh*DH + dh)*TT + t0;
                uint4* ph4 = (uint4*)(Vh_ + base);
                uint4* pl4 = (uint4*)(Vl_ + base);
                for (int q = 0; q < 4; q++) { ph4[q] = hv[q]; pl4[q] = lv[q]; }
            }
        } else if (col < N) {
            float bi = bias ? bias[col] : 0.f;
            for (int j2 = 0; j2 < 32; j2++) {
                float v = tp2[j2*33+lid] + bi;
                int row = rb + sp*32 + j2;
                if (RES) v += res[(size_t)row*N + col];
                if (ACT) v = 0.5f*v*(1.0f + erff(v*0.70710678118654752f));
                if (MODE == 1) {
                    __nv_bfloat16 hi, lo; split_bf16(v, hi, lo);
                    Cb[(size_t)row*N+col] = hi; Clo[(size_t)row*N+col] = lo;
                } else Cf[(size_t)row*N+col] = v;
            }
        }
        __syncwarp();
    }
    __syncthreads();
    if (wid == 0) {
        asm volatile("tcgen05.dealloc.cta_group::2.sync.aligned.b32 %0, %1;"
                     :: "r"(tmem), "r"(256u));
    }
    cluster_sync();
#else
    if (threadIdx.x == 0 && blockIdx.x == 0) { }   // fallback stub (cubin path runs on HW)
#endif
}

// ---------------- tcgen05 flash attention (unchanged) ----------------
#define AO_MB1 8
#define AO_MB2 16
#define AO_M   32
#define AO_L   (AO_M+512)
#define AO_AL  (AO_L+512)
#define AO_PMX (AO_AL+512)
#define AO_PSM (AO_PMX+1024)
#define AO_Q   4096
#define AO_QL  (AO_Q+16384)
#define AO_KH  (AO_QL+16384)
#define AO_KL  (AO_KH+16384)
#define AO_V0H (AO_KL+16384)
#define AO_V0L (AO_V0H+8192)
#define AO_V1H (AO_V0L+8192)
#define AO_V1L (AO_V1H+8192)
#define AO_PAH (AO_V1L+8192)
#define AO_PAL (AO_PAH+16384)
#define AO_PBH (AO_PAL+16384)
#define AO_PBL (AO_PBH+16384)
#define SMEMA  (AO_PBL+16384)
#define IDESC_S (0x490u | (16u<<17) | (8u<<24))
#define IDESC_O (0x490u | (8u<<17)  | (8u<<24))

__global__ void __launch_bounds__(256)
attn_tc_k(const __nv_bfloat16* __restrict__ Qh, const __nv_bfloat16* __restrict__ Ql,
          const __nv_bfloat16* __restrict__ Kh, const __nv_bfloat16* __restrict__ Kl,
          const __nv_bfloat16* __restrict__ Vth, const __nv_bfloat16* __restrict__ Vtl,
          __nv_bfloat16* __restrict__ yh, __nv_bfloat16* __restrict__ yl)
{
#if HAS_TC
    extern __shared__ __align__(1024) char smc[];
    uint32_t sb = smem_u32(smc);
    const int tid = threadIdx.x, wid = tid>>5, lid = tid&31;
    const int sp = wid&3, nh = wid>>2;
    const int bh = blockIdx.y, b = bh>>4, h = bh&15;
    const int qs = blockIdx.x*128;
    if (wid == 0) {
        asm volatile("tcgen05.alloc.cta_group::1.sync.aligned.shared::cta.b32 [%0], %1;"
                     :: "r"(sb), "r"(256u) : "memory");
        asm volatile("tcgen05.relinquish_alloc_permit.cta_group::1.sync.aligned;");
    }
    if (tid == 0) { mbar_init(sb+AO_MB1, 1); mbar_init(sb+AO_MB2, 1); }
    float* Mrow = (float*)(smc+AO_M);
    float* Lrow = (float*)(smc+AO_L);
    float* Arow = (float*)(smc+AO_AL);
    float* Pmax = (float*)(smc+AO_PMX);
    float* Psum = (float*)(smc+AO_PSM);
    if (tid < 128) { Mrow[tid] = -1e30f; Lrow[tid] = 0.f; }
    __syncthreads();
    uint32_t tmem;
    asm volatile("ld.shared.b32 %0, [%1];" : "=r"(tmem) : "r"(sb));
    {
        size_t qb = ((size_t)bh*TT + qs)*DH;
        for (int j = 0; j < 4; j++) {
            int i = tid + j*256, r = i>>3, u = i&7;
            int off = r*128 + u*16, sw = off ^ ((off>>3)&0x70);
            *(uint4*)(smc+AO_Q +sw) = *(const uint4*)(Qh + qb + (size_t)r*DH + u*8);
            *(uint4*)(smc+AO_QL+sw) = *(const uint4*)(Ql + qb + (size_t)r*DH + u*8);
        }
    }
    const int r = sp*32 + lid;
    const int jmax = max(qs + r, KMIN);
    const int nt = (max(qs+127, KMIN) + 128)/128;
    uint32_t ph1 = 0, ph2 = 0;
    for (int kt = 0; kt < nt; kt++) {
        int ks0 = kt*128;
        {
            size_t kb = ((size_t)bh*TT + ks0)*DH;
            for (int j = 0; j < 4; j++) {
                int i = tid + j*256, rr = i>>3, u = i&7;
                int off = rr*128 + u*16, sw = off ^ ((off>>3)&0x70);
                *(uint4*)(smc+AO_KH+sw) = *(const uint4*)(Kh + kb + (size_t)rr*DH + u*8);
                *(uint4*)(smc+AO_KL+sw) = *(const uint4*)(Kl + kb + (size_t)rr*DH + u*8);
            }
            for (int j = 0; j < 4; j++) {
                int i = tid + j*256, rr = i>>4, u = i&15;
                int off = rr*128 + (u&7)*16, sw = off ^ ((off>>3)&0x70);
                size_t src = ((size_t)bh*DH + rr)*TT + ks0 + u*8;
                int th_ = (u<8)?AO_V0H:AO_V1H, tl_ = (u<8)?AO_V0L:AO_V1L;
                *(uint4*)(smc+th_+sw) = *(const uint4*)(Vth + src);
                *(uint4*)(smc+tl_+sw) = *(const uint4*)(Vtl + src);
            }
        }
        asm volatile("fence.proxy.async.shared::cta;" ::: "memory");
        __syncthreads();
        if (wid == 0 && elect_one()) {
            uint64_t dqh = mk_desc(sb+AO_Q),  dql = mk_desc(sb+AO_QL);
            uint64_t dkh = mk_desc(sb+AO_KH), dkl = mk_desc(sb+AO_KL);
            for (int ks = 0; ks < 4; ks++) {
                uint64_t o = ks*2;
                mma_f16_ss(tmem, dqh+o, dkh+o, IDESC_S, ks>0 ? 1u:0u);
                mma_f16_ss(tmem, dqh+o, dkl+o, IDESC_S, 1u);
                mma_f16_ss(tmem, dql+o, dkh+o, IDESC_S, 1u);
            }
            tc_commit(sb+AO_MB1);
        }
        mbar_wait(sb+AO_MB1, ph1); ph1 ^= 1;
        asm volatile("tcgen05.fence::after_thread_sync;" ::: "memory");
        float s[64];
        {
            uint32_t t0[32], t1[32];
            TC_LD32(t0, tmem + ((uint32_t)sp<<21) + nh*64);
            TC_LD32(t1, tmem + ((uint32_t)sp<<21) + nh*64 + 32);
            asm volatile("tcgen05.wait::ld.sync.aligned;" ::: "memory");
            for (int j = 0; j < 32; j++) { s[j] = __uint_as_float(t0[j]); s[32+j] = __uint_as_float(t1[j]); }
        }
        float lmax = -1e30f;
        for (int j = 0; j < 64; j++) {
            int jc = ks0 + nh*64 + j;
            s[j] = (jc <= jmax) ? s[j]*0.125f : -1e30f;
            lmax = fmaxf(lmax, s[j]);
        }
        Pmax[nh*128 + r] = lmax;
        __syncthreads();
        float m_old = Mrow[r];
        float m_new = fmaxf(m_old, fmaxf(Pmax[r], Pmax[128+r]));
        float al = __expf(m_old - m_new);
        float lsum = 0.f;
        {
            int pbh = nh ? AO_PBH : AO_PAH, pbl = nh ? AO_PBL : AO_PAL;
            for (int j2 = 0; j2 < 32; j2++) {
                float p0 = __expf(s[2*j2]   - m_new);
                float p1 = __expf(s[2*j2+1] - m_new);
                lsum += p0 + p1;
                __nv_bfloat16 h0, l0, h1, l1;
                split_bf16(p0, h0, l0); split_bf16(p1, h1, l1);
                int off = r*128 + j2*4, sw = off ^ ((off>>3)&0x70);
                *(uint32_t*)(smc+pbh+sw) = ((uint32_t)__bfloat16_as_ushort(h1)<<16) | __bfloat16_as_ushort(h0);
                *(uint32_t*)(smc+pbl+sw) = ((uint32_t)__bfloat16_as_ushort(l1)<<16) | __bfloat16_as_ushort(l0);
            }
        }
        Psum[nh*128 + r] = lsum;
        if (nh == 0) Arow[r] = al;
        __syncthreads();
        if (wid < 4) { Lrow[r] = Lrow[r]*al + Psum[r] + Psum[128+r]; Mrow[r] = m_new; }
        if (kt > 0) {
            uint32_t oaddr = tmem + ((uint32_t)sp<<21) + 128 + nh*32;
            uint32_t o32[32];
            TC_LD32(o32, oaddr);
            asm volatile("tcgen05.wait::ld.sync.aligned;" ::: "memory");
            float a = Arow[r];
            for (int j = 0; j < 32; j++) o32[j] = __float_as_uint(__uint_as_float(o32[j])*a);
            TC_ST32(oaddr, o32);
            asm volatile("tcgen05.wait::st.sync.aligned;" ::: "memory");
        }
        asm volatile("tcgen05.fence::before_thread_sync;" ::: "memory");
        asm volatile("fence.proxy.async.shared::cta;" ::: "memory");
        __syncthreads();
        if (wid == 0 && elect_one()) {
            asm volatile("tcgen05.fence::after_thread_sync;" ::: "memory");
            uint64_t dp[4] = { mk_desc(sb+AO_PAH), mk_desc(sb+AO_PBH),
                               mk_desc(sb+AO_PAL), mk_desc(sb+AO_PBL) };
            uint64_t dv[4] = { mk_desc(sb+AO_V0H), mk_desc(sb+AO_V1H),
                               mk_desc(sb+AO_V0L), mk_desc(sb+AO_V1L) };
            for (int ks = 0; ks < 8; ks++) {
                int g = ks>>2;
                uint64_t o = (uint64_t)(ks&3)*2;
                uint32_t en = (kt==0 && ks==0) ? 0u : 1u;
                mma_f16_ss(tmem+128, dp[g]+o,   dv[g]+o,   IDESC_O, en);
                mma_f16_ss(tmem+128, dp[g]+o,   dv[g+2]+o, IDESC_O, 1u);
                mma_f16_ss(tmem+128, dp[g+2]+o, dv[g]+o,   IDESC_O, 1u);
            }
            tc_commit(sb+AO_MB2);
        }
        mbar_wait(sb+AO_MB2, ph2); ph2 ^= 1;
        asm volatile("tcgen05.fence::after_thread_sync;" ::: "memory");
        __syncthreads();
    }
    {
        uint32_t o32[32];
        TC_LD32(o32, tmem + ((uint32_t)sp<<21) + 128 + nh*32);
        asm volatile("tcgen05.wait::ld.sync.aligned;" ::: "memory");
        float linv = 1.f/Lrow[r];
        float* tp = (float*)(smc+AO_PAH) + wid*(32*33);
        for (int j = 0; j < 32; j++) tp[lid*33+j] = __uint_as_float(o32[j])*linv;
        __syncwarp();
        for (int j2 = 0; j2 < 32; j2++) {
            float v = tp[j2*33+lid];
            int grow = qs + sp*32 + j2;
            int gcol = h*DH + nh*32 + lid;
            __nv_bfloat16 hi, lo; split_bf16(v, hi, lo);
            size_t go = ((size_t)b*TT + grow)*DD + gcol;
            yh[go] = hi; yl[go] = lo;
        }
    }
    __syncthreads();
    if (wid == 0)
        asm volatile("tcgen05.dealloc.cta_group::1.sync.aligned.b32 %0, %1;"
                     :: "r"(tmem), "r"(256u));
#else
    int bh = blockIdx.y, b = bh>>4, h = bh&15;
    if (threadIdx.x >= 128) return;
    int qi = blockIdx.x*128 + threadIdx.x;
    float q[DH], o[DH];
    size_t qb = ((size_t)bh*TT + qi)*DH;
    for (int d = 0; d < DH; d++) {
        q[d] = __bfloat162float(Qh[qb+d]) + __bfloat162float(Ql[qb+d]); o[d] = 0.f;
    }
    float m = -1e30f, l = 0.f;
    int jm = max(qi, KMIN);
    for (int j = 0; j <= jm; j++) {
        size_t kb = ((size_t)bh*TT + j)*DH;
        float s = 0.f;
        for (int d = 0; d < DH; d++)
            s += q[d]*(__bfloat162float(Kh[kb+d]) + __bfloat162float(Kl[kb+d]));
        s *= 0.125f;
        float mn = fmaxf(m, s), al = __expf(m-mn), p = __expf(s-mn);
        l = l*al + p;
        for (int d = 0; d < DH; d++) {
            size_t vo = ((size_t)bh*DH + d)*TT + j;
            o[d] = o[d]*al + p*(__bfloat162float(Vth[vo]) + __bfloat162float(Vtl[vo]));
        }
        m = mn;
    }
    for (int d = 0; d < DH; d++) {
        __nv_bfloat16 hi, lo; split_bf16(o[d]/l, hi, lo);
        size_t go = ((size_t)b*TT + qi)*DD + h*DH + d;
        yh[go] = hi; yl[go] = lo;
    }
#endif
}

// ---------------- host ----------------
typedef CUresult (*tmap_fn_t)(CUtensorMap*, CUtensorMapDataType, cuuint32_t, void*,
                              const cuuint64_t*, const cuuint64_t*, const cuuint32_t*,
                              const cuuint32_t*, CUtensorMapInterleave, CUtensorMapSwizzle,
                              CUtensorMapL2promotion, CUtensorMapFloatOOBfill);

static void mk_map(tmap_fn_t fn, CUtensorMap* m, void* p,
                   uint64_t d0, uint64_t d1, uint64_t d2, uint32_t box1) {
    cuuint64_t dims[3] = {d0, d1, d2};
    cuuint64_t strides[2] = {d0*2, d0*d1*2};
    cuuint32_t box[3] = {64, box1, 1};
    cuuint32_t es[3] = {1, 1, 1};
    fn(m, CU_TENSOR_MAP_DATA_TYPE_BFLOAT16, 3, p, dims, strides, box, es,
       CU_TENSOR_MAP_INTERLEAVE_NONE, CU_TENSOR_MAP_SWIZZLE_128B,
       CU_TENSOR_MAP_L2_PROMOTION_L2_128B, CU_TENSOR_MAP_FLOAT_OOB_FILL_NONE);
}

extern "C" void kernel_launch(void* const* d_in, const int* in_sizes, int n_in,
                              void* d_out, int out_size) {
    const int*   idx     = (const int*)  d_in[0];
    const float* tok_emb = (const float*)d_in[1];
    const float* ln1_w = (const float*)d_in[2],  *ln1_b = (const float*)d_in[3];
    const float* Wq = (const float*)d_in[4],  *bq = (const float*)d_in[5];
    const float* Wk = (const float*)d_in[6],  *bk = (const float*)d_in[7];
    const float* Wv = (const float*)d_in[8],  *bv = (const float*)d_in[9];
    const float* Wp = (const float*)d_in[10], *bp = (const float*)d_in[11];
    const float* ln2_w = (const float*)d_in[12], *ln2_b = (const float*)d_in[13];
    const float* W1 = (const float*)d_in[14], *b1 = (const float*)d_in[15];
    const float* W2 = (const float*)d_in[16], *b2 = (const float*)d_in[17];
    const float* lnf_w = (const float*)d_in[18], *lnf_b = (const float*)d_in[19];
    const float* head_w = (const float*)d_in[20];
    float* out = (float*)d_out;

    float *x, *bqkv;
    __nv_bfloat16 *hh,*hl,*yh,*yl,*m1h,*m1l,*qah,*qal,*kah,*kal,*vth,*vtl;
    __nv_bfloat16 *wqkvh,*wqkvl,*wph,*wpl,*w1h,*w1l,*w2h,*w2l,*whh,*whl;
    cudaGetSymbolAddress((void**)&x, g_x);
    cudaGetSymbolAddress((void**)&hh, g_hh);   cudaGetSymbolAddress((void**)&hl, g_hl);
    cudaGetSymbolAddress((void**)&yh, g_yh);   cudaGetSymbolAddress((void**)&yl, g_yl);
    cudaGetSymbolAddress((void**)&m1h, g_m1h); cudaGetSymbolAddress((void**)&m1l, g_m1l);
    cudaGetSymbolAddress((void**)&qah, g_qah); cudaGetSymbolAddress((void**)&qal, g_qal);
    cudaGetSymbolAddress((void**)&kah, g_kah); cudaGetSymbolAddress((void**)&kal, g_kal);
    cudaGetSymbolAddress((void**)&vth, g_vth); cudaGetSymbolAddress((void**)&vtl, g_vtl);
    cudaGetSymbolAddress((void**)&wqkvh, g_wqkvh); cudaGetSymbolAddress((void**)&wqkvl, g_wqkvl);
    cudaGetSymbolAddress((void**)&wph, g_wph); cudaGetSymbolAddress((void**)&wpl, g_wpl);
    cudaGetSymbolAddress((void**)&w1h, g_w1h); cudaGetSymbolAddress((void**)&w1l, g_w1l);
    cudaGetSymbolAddress((void**)&w2h, g_w2h); cudaGetSymbolAddress((void**)&w2l, g_w2l);
    cudaGetSymbolAddress((void**)&whh, g_whh); cudaGetSymbolAddress((void**)&whl, g_whl);
    cudaGetSymbolAddress((void**)&bqkv, g_bqkv);

    static tmap_fn_t fn = nullptr;
    if (!fn) {
        cudaDriverEntryPointQueryResult st;
        cudaGetDriverEntryPoint("cuTensorMapEncodeTiled", (void**)&fn,
                                cudaEnableDefault, &st);
    }
    static CUtensorMap mAh, mAl, mYh, mYl, mMh, mMl;
    static CUtensorMap mQKVh, mQKVl, mPh, mPl, mW1h, mW1l, mW2h, mW2l, mHh, mHl;
    mk_map(fn, &mAh, hh, DD, MM_, 1, 128);   mk_map(fn, &mAl, hl, DD, MM_, 1, 128);
    mk_map(fn, &mYh, yh, DD, MM_, 1, 128);   mk_map(fn, &mYl, yl, DD, MM_, 1, 128);
    mk_map(fn, &mMh, m1h, FF, MM_, 1, 128);  mk_map(fn, &mMl, m1l, FF, MM_, 1, 128);
    mk_map(fn, &mQKVh, wqkvh, DD, QKVN, LL, 128); mk_map(fn, &mQKVl, wqkvl, DD, QKVN, LL, 128);
    mk_map(fn, &mPh, wph, DD, DD, LL, 128);  mk_map(fn, &mPl, wpl, DD, DD, LL, 128);
    mk_map(fn, &mW1h, w1h, DD, FF, LL, 128); mk_map(fn, &mW1l, w1l, DD, FF, LL, 128);
    mk_map(fn, &mW2h, w2h, FF, DD, LL, 128); mk_map(fn, &mW2l, w2l, FF, DD, LL, 128);
    mk_map(fn, &mHh, whh, DD, VPAD, 1, 128); mk_map(fn, &mHl, whl, DD, VPAD, 1, 128);

    cudaFuncSetAttribute(tgemm_k<0,0,0>, cudaFuncAttributeMaxDynamicSharedMemorySize, SMEMB);
    cudaFuncSetAttribute(tgemm_k<0,0,1>, cudaFuncAttributeMaxDynamicSharedMemorySize, SMEMB);
    cudaFuncSetAttribute(tgemm_k<1,1,0>, cudaFuncAttributeMaxDynamicSharedMemorySize, SMEMB);
    cudaFuncSetAttribute(tgemm_k<0,2,0>, cudaFuncAttributeMaxDynamicSharedMemorySize, SMEMB);
    cudaFuncSetAttribute(attn_tc_k, cudaFuncAttributeMaxDynamicSharedMemorySize, SMEMA);

    dim3 tb(32, 8);
    dim3 gQKV (MM_/MT, QKVN/NT), gPROJ(MM_/MT, DD/NT);
    dim3 gMLP1(MM_/MT, FF/NT),   gHEAD(MM_/MT, VPAD/NT);
    dim3 gAtt (TT/128, BB*HH);

    convqkv3_k<<<dim3(DD/32, DD/32, 3*LL), tb>>>(Wq, Wk, Wv, wqkvh, wqkvl);
    embed_k<<<MM_, 256>>>(idx, tok_emb, x, bq, bk, bv, bqkv);
    ln_k<<<MM_, 256>>>(x, ln1_w, ln1_b, hh, hl);
    tgemm_k<0,2,0><<<gQKV, 256, SMEMB>>>(mAh, mAl, mQKVh, mQKVl, 0,
        bqkv, nullptr, nullptr, nullptr, qah, qal, kah, kal, vth, vtl, MM_, QKVN, DD);
    convT_k<<<dim3(DD/32, DD/32, LL), tb>>>(Wp, (size_t)DD*DD, wph, wpl, (size_t)DD*DD, DD, DD);
    convT_k<<<dim3(FF/32, DD/32, LL), tb>>>(W1, (size_t)DD*FF, w1h, w1l, (size_t)DD*FF, DD, FF);
    convT_k<<<dim3(DD/32, FF/32, LL), tb>>>(W2, (size_t)DD*FF, w2h, w2l, (size_t)DD*FF, FF, DD);
    convT_k<<<dim3(VPAD/32, DD/32, 1), tb>>>(head_w, 0, whh, whl, 0, DD, VV);

    for (int l = 0; l < LL; l++) {
        size_t oD = (size_t)l*DD;
        if (l > 0) {
            ln_k<<<MM_, 256>>>(x, ln1_w+oD, ln1_b+oD, hh, hl);
            tgemm_k<0,2,0><<<gQKV, 256, SMEMB>>>(mAh, mAl, mQKVh, mQKVl, l,
                bqkv+l*QKVN, nullptr, nullptr, nullptr, qah, qal, kah, kal, vth, vtl,
                MM_, QKVN, DD);
        }
        attn_tc_k<<<gAtt, 256, SMEMA>>>(qah, qal, kah, kal, vth, vtl, yh, yl);
        tgemm_k<0,0,1><<<gPROJ, 256, SMEMB>>>(mYh, mYl, mPh, mPl, l,
            bp+oD, x, x, nullptr, nullptr, nullptr, nullptr, nullptr, nullptr, nullptr,
            MM_, DD, DD);
        ln_k<<<MM_, 256>>>(x, ln2_w+oD, ln2_b+oD, hh, hl);
        tgemm_k<1,1,0><<<gMLP1, 256, SMEMB>>>(mAh, mAl, mW1h, mW1l, l,
            b1+(size_t)l*FF, nullptr, m1h, m1l, nullptr, nullptr, nullptr, nullptr, nullptr, nullptr,
            MM_, FF, DD);
        tgemm_k<0,0,1><<<gPROJ, 256, SMEMB>>>(mMh, mMl, mW2h, mW2l, l,
            b2+oD, x, x, nullptr, nullptr, nullptr, nullptr, nullptr, nullptr, nullptr,
            MM_, DD, FF);
    }
    ln_k<<<MM_, 256>>>(x, lnf_w, lnf_b, hh, hl);
    tgemm_k<0,0,0><<<gHEAD, 256, SMEMB>>>(mAh, mAl, mHh, mHl, 0,
        nullptr, nullptr, out, nullptr, nullptr, nullptr, nullptr, nullptr, nullptr, nullptr,
        MM_, VV, DD);
}